// round 1
// baseline (speedup 1.0000x reference)
#include <cuda_runtime.h>

#define DFT 784
#define KC 50
#define LF 6
#define NB 2
#define THREADS 256
#define NWARPS (THREADS/32)

// Packed per-(k,d) operand: {a0,a1,a2,a3} {a4,a5,invD,mu}
__device__ __align__(16) float4 g_Apack[KC * DFT * 2];

__device__ __forceinline__ constexpr int IJ(int i, int j) { return i * (i + 1) / 2 + j; }

__global__ void pack_kernel(const float* __restrict__ A_fac,
                            const float* __restrict__ MU,
                            const float* __restrict__ log_D)
{
    int idx = blockIdx.x * blockDim.x + threadIdx.x;
    if (idx >= KC * DFT) return;
    const float* a = A_fac + (size_t)idx * LF;
    float invD = expf(-log_D[idx]);
    g_Apack[idx * 2 + 0] = make_float4(a[0], a[1], a[2], a[3]);
    g_Apack[idx * 2 + 1] = make_float4(a[4], a[5], invD, MU[idx]);
}

// Cholesky (lower) of packed 6x6 SPD matrix, in place. Returns product of pivots
// (= det(P)), fills inv[j] = 1/L[j][j].
__device__ __forceinline__ float chol6(float* S, float* inv)
{
    float prod = 1.f;
    #pragma unroll
    for (int j = 0; j < LF; j++) {
        float s = S[IJ(j, j)];
        #pragma unroll
        for (int m = 0; m < j; m++) s = fmaf(-S[IJ(j, m)], S[IJ(j, m)], s);
        prod *= s;
        float rs = rsqrtf(s);
        inv[j] = rs;
        S[IJ(j, j)] = s * rs;
        #pragma unroll
        for (int i = j + 1; i < LF; i++) {
            float t = S[IJ(i, j)];
            #pragma unroll
            for (int m = 0; m < j; m++) t = fmaf(-S[IJ(i, m)], S[IJ(j, m)], t);
            S[IJ(i, j)] = t * rs;
        }
    }
    return prod;
}

// Forward solve L y = q; returns |y|^2.
__device__ __forceinline__ float fwd6(const float* L, const float* inv, const float* q, float* y)
{
    float ysq = 0.f;
    #pragma unroll
    for (int i = 0; i < LF; i++) {
        float t = q[i];
        #pragma unroll
        for (int m = 0; m < i; m++) t = fmaf(-L[IJ(i, m)], y[m], t);
        y[i] = t * inv[i];
        ysq = fmaf(y[i], y[i], ysq);
    }
    return ysq;
}

__global__ __launch_bounds__(THREADS, 2)
void mfa_main(const float* __restrict__ X, const int* __restrict__ J,
              const float* __restrict__ log_D, const float* __restrict__ PI,
              float* __restrict__ outPw, float* __restrict__ outM,
              float* __restrict__ outA, float* __restrict__ outD)
{
    __shared__ float2 s_in[NB][DFT];           // {jf, x*jf}
    __shared__ float  s_pi[KC];
    __shared__ float  s_bscore[NWARPS][NB];
    __shared__ int    s_bk[NWARPS][NB];
    __shared__ float  s_bPq[NWARPS][NB][27];   // P(with +I) 21, q 6
    __shared__ float  s_mz[NB][LF];
    __shared__ float  s_Lzm[NB][21];
    __shared__ int    s_c[NB];

    const int tid  = threadIdx.x;
    const int lane = tid & 31;
    const int warp = tid >> 5;
    const int b0   = blockIdx.x * NB;

    // Load sample rows into smem
    for (int t = tid; t < DFT; t += THREADS) {
        #pragma unroll
        for (int b2 = 0; b2 < NB; b2++) {
            float x  = X[(size_t)(b0 + b2) * DFT + t];
            float jf = (J[(size_t)(b0 + b2) * DFT + t] == 1) ? 1.0f : 0.0f;
            s_in[b2][t] = make_float2(jf, x * jf);
        }
    }
    for (int t = tid; t < KC; t += THREADS) s_pi[t] = PI[t];
    if (lane == 0) {
        #pragma unroll
        for (int b2 = 0; b2 < NB; b2++) s_bscore[warp][b2] = -1e30f;
    }
    __syncthreads();

    // ---- Phase 1: per-(k, sample-pair) reductions, warp-parallel over k ----
    for (int k = warp; k < KC; k += NWARPS) {
        float acc[NB][29];   // [0..20] P, [21..26] q, [27] quad, [28] Jf.logD
        #pragma unroll
        for (int b2 = 0; b2 < NB; b2++)
            #pragma unroll
            for (int t = 0; t < 29; t++) acc[b2][t] = 0.f;

        const float4* __restrict__ ap  = g_Apack + (size_t)k * DFT * 2;
        const float*  __restrict__ ldp = log_D   + (size_t)k * DFT;

        for (int d = lane; d < DFT; d += 32) {
            float4 v0 = ap[d * 2 + 0];
            float4 v1 = ap[d * 2 + 1];
            float a[LF] = {v0.x, v0.y, v0.z, v0.w, v1.x, v1.y};
            float invD = v1.z, mu = v1.w;
            float ldg = __ldg(ldp + d);
            float ia[LF];
            #pragma unroll
            for (int i = 0; i < LF; i++) ia[i] = invD * a[i];

            #pragma unroll
            for (int b2 = 0; b2 < NB; b2++) {
                float2 in = s_in[b2][d];
                float jf = in.x, xj = in.y;
                float md = fmaf(-mu, jf, xj);            // masked residual
                acc[b2][27] = fmaf(md * md, invD, acc[b2][27]);
                acc[b2][28] = fmaf(jf, ldg, acc[b2][28]);
                float ja[LF];
                #pragma unroll
                for (int i = 0; i < LF; i++) {
                    acc[b2][21 + i] = fmaf(md, ia[i], acc[b2][21 + i]);
                    ja[i] = jf * ia[i];
                }
                #pragma unroll
                for (int i = 0; i < LF; i++)
                    #pragma unroll
                    for (int j = 0; j <= i; j++)
                        acc[b2][IJ(i, j)] = fmaf(ja[i], a[j], acc[b2][IJ(i, j)]);
            }
        }

        // Warp butterfly reduce (all lanes end with totals)
        #pragma unroll
        for (int b2 = 0; b2 < NB; b2++)
            #pragma unroll
            for (int t = 0; t < 29; t++) {
                float v = acc[b2][t];
                #pragma unroll
                for (int off = 16; off > 0; off >>= 1)
                    v += __shfl_xor_sync(0xffffffffu, v, off);
                acc[b2][t] = v;
            }

        if (lane == 0) {
            #pragma unroll
            for (int b2 = 0; b2 < NB; b2++) {
                float P[21], q[LF];
                #pragma unroll
                for (int t = 0; t < 21; t++) P[t] = acc[b2][t];
                #pragma unroll
                for (int i = 0; i < LF; i++) { P[IJ(i, i)] += 1.0f; q[i] = acc[b2][21 + i]; }
                float inv[LF];
                float prod = chol6(P, inv);              // det(P) = prod of pivots
                float y[LF];
                float ysq = fwd6(P, inv, q, y);
                // score = PI_k - 0.5*(quad - |y|^2 + log det P + Jf.logD)
                float score = s_pi[k] - 0.5f * (acc[b2][27] - ysq + __logf(prod) + acc[b2][28]);
                if (score > s_bscore[warp][b2]) {
                    s_bscore[warp][b2] = score;
                    s_bk[warp][b2] = k;
                    // store P WITH identity, pre-Cholesky values were overwritten; rebuild raw:
                    #pragma unroll
                    for (int t = 0; t < 21; t++) s_bPq[warp][b2][t] = acc[b2][t];
                    #pragma unroll
                    for (int i = 0; i < LF; i++) s_bPq[warp][b2][21 + i] = q[i];
                }
            }
        }
    }
    __syncthreads();

    // ---- Phase 2: per-sample small linalg (one thread per sample) ----
    if (tid < NB) {
        const int b2 = tid;
        float best = -1e30f; int bw = 0;
        for (int w = 0; w < NWARPS; w++)
            if (s_bscore[w][b2] > best) { best = s_bscore[w][b2]; bw = w; }
        s_c[b2] = s_bk[bw][b2];

        float P[21], q[LF];
        #pragma unroll
        for (int t = 0; t < 21; t++) P[t] = s_bPq[bw][b2][t];
        #pragma unroll
        for (int i = 0; i < LF; i++) { P[IJ(i, i)] += 1.0f; q[i] = s_bPq[bw][b2][21 + i]; }

        float inv[LF];
        (void)chol6(P, inv);                             // P now holds L
        float y[LF];
        (void)fwd6(P, inv, q, y);
        float mz[LF];
        #pragma unroll
        for (int ii = LF - 1; ii >= 0; ii--) {
            float t = y[ii];
            #pragma unroll
            for (int m = ii + 1; m < LF; m++) t = fmaf(-P[IJ(m, ii)], mz[m], t);
            mz[ii] = t * inv[ii];
        }
        // Linv (lower) via forward substitution on identity
        float Li[21];
        #pragma unroll
        for (int j = 0; j < LF; j++) {
            Li[IJ(j, j)] = inv[j];
            #pragma unroll
            for (int i = j + 1; i < LF; i++) {
                float t = 0.f;
                #pragma unroll
                for (int m = j; m < i; m++) t = fmaf(P[IJ(i, m)], Li[IJ(m, j)], t);
                Li[IJ(i, j)] = -inv[i] * t;
            }
        }
        // cov = Linv^T Linv (lower packed)
        float C[21];
        #pragma unroll
        for (int i = 0; i < LF; i++)
            #pragma unroll
            for (int j = 0; j <= i; j++) {
                float t = 0.f;
                #pragma unroll
                for (int m = i; m < LF; m++) t = fmaf(Li[IJ(m, i)], Li[IJ(m, j)], t);
                C[IJ(i, j)] = t;
            }
        float invz[LF];
        (void)chol6(C, invz);                            // C now holds Lz
        #pragma unroll
        for (int i = 0; i < LF; i++) s_mz[b2][i] = mz[i];
        #pragma unroll
        for (int t = 0; t < 21; t++) s_Lzm[b2][t] = C[t];
    }
    __syncthreads();

    // ---- Epilogue: stream outputs ----
    #pragma unroll
    for (int b2 = 0; b2 < NB; b2++) {
        const int b = b0 + b2;
        const int c = s_c[b2];
        float mz[LF], Lz[21];
        #pragma unroll
        for (int i = 0; i < LF; i++) mz[i] = s_mz[b2][i];
        #pragma unroll
        for (int t = 0; t < 21; t++) Lz[t] = s_Lzm[b2][t];
        const float4* __restrict__ apc = g_Apack + (size_t)c * DFT * 2;
        const float*  __restrict__ ldc = log_D + (size_t)c * DFT;
        for (int d = tid; d < DFT; d += THREADS) {
            float4 v0 = apc[d * 2 + 0];
            float4 v1 = apc[d * 2 + 1];
            float a[LF] = {v0.x, v0.y, v0.z, v0.w, v1.x, v1.y};
            float mu = v1.w;
            float Mo = mu;
            #pragma unroll
            for (int i = 0; i < LF; i++) Mo = fmaf(a[i], mz[i], Mo);
            outM[(size_t)b * DFT + d] = Mo;
            float Ao[LF];
            #pragma unroll
            for (int j = 0; j < LF; j++) {
                float s = 0.f;
                #pragma unroll
                for (int i = j; i < LF; i++) s = fmaf(a[i], Lz[IJ(i, j)], s);
                Ao[j] = s;
            }
            float2* pA = reinterpret_cast<float2*>(outA + ((size_t)b * DFT + d) * LF);
            pA[0] = make_float2(Ao[0], Ao[1]);
            pA[1] = make_float2(Ao[2], Ao[3]);
            pA[2] = make_float2(Ao[4], Ao[5]);
            outD[(size_t)b * DFT + d] = expf(ldc[d]);
        }
    }
    if (tid < NB) outPw[b0 + tid] = 1.0f;
}

extern "C" void kernel_launch(void* const* d_in, const int* in_sizes, int n_in,
                              void* d_out, int out_size)
{
    const float* X      = (const float*)d_in[0];
    const int*   J      = (const int*)  d_in[1];
    const float* MU     = (const float*)d_in[2];
    const float* A_fac  = (const float*)d_in[3];
    const float* log_D  = (const float*)d_in[4];
    const float* PI     = (const float*)d_in[5];
    float* out = (float*)d_out;

    const int B = in_sizes[0] / DFT;     // 2048
    float* outPw = out;
    float* outM  = out + B;
    float* outA  = outM + (size_t)B * DFT;
    float* outD  = outA + (size_t)B * DFT * LF;

    pack_kernel<<<(KC * DFT + 255) / 256, 256>>>(A_fac, MU, log_D);
    mfa_main<<<B / NB, THREADS>>>(X, J, log_D, PI, outPw, outM, outA, outD);
}

// round 2
// speedup vs baseline: 1.3345x; 1.3345x over previous
#include <cuda_runtime.h>

#define DFT 784
#define DP  800              // padded feature dim (zero-padded tail)
#define KC  50
#define LF  6
#define NB  2
#define THREADS 160
#define NWARPS (THREADS/32)  // 5 -> each warp does exactly 10 components
#define NITER 25             // ceil(800/32)

typedef unsigned long long u64;

// Packed per-(k,d) operand: {a0,a1,a2,a3} {a4,a5,logD,mu}, k-stride DP, zero padded.
__device__ __align__(16) float4 g_Apack[KC * DP * 2];

__device__ __forceinline__ constexpr int IJ(int i, int j) { return i * (i + 1) / 2 + j; }

// ---- f32x2 packed helpers (PTX ISA 8.6, sm_100a) ----
__device__ __forceinline__ u64 pk2(float a, float b) {
    u64 r; asm("mov.b64 %0,{%1,%2};" : "=l"(r) : "f"(a), "f"(b)); return r;
}
__device__ __forceinline__ u64 rep2(float a) { return pk2(a, a); }
__device__ __forceinline__ void upk2(u64 v, float& a, float& b) {
    asm("mov.b64 {%0,%1},%2;" : "=f"(a), "=f"(b) : "l"(v));
}
__device__ __forceinline__ u64 fma2(u64 a, u64 b, u64 c) {
    u64 d; asm("fma.rn.f32x2 %0,%1,%2,%3;" : "=l"(d) : "l"(a), "l"(b), "l"(c)); return d;
}
__device__ __forceinline__ u64 mul2(u64 a, u64 b) {
    u64 d; asm("mul.rn.f32x2 %0,%1,%2;" : "=l"(d) : "l"(a), "l"(b)); return d;
}
__device__ __forceinline__ u64 add2(u64 a, u64 b) {
    u64 d; asm("add.rn.f32x2 %0,%1,%2;" : "=l"(d) : "l"(a), "l"(b)); return d;
}

__global__ void pack_kernel(const float* __restrict__ A_fac,
                            const float* __restrict__ MU,
                            const float* __restrict__ log_D)
{
    int idx = blockIdx.x * blockDim.x + threadIdx.x;
    if (idx >= KC * DP) return;
    int k = idx / DP, d = idx % DP;
    if (d < DFT) {
        int src = k * DFT + d;
        const float* a = A_fac + (size_t)src * LF;
        g_Apack[idx * 2 + 0] = make_float4(a[0], a[1], a[2], a[3]);
        g_Apack[idx * 2 + 1] = make_float4(a[4], a[5], log_D[src], MU[src]);
    } else {
        g_Apack[idx * 2 + 0] = make_float4(0.f, 0.f, 0.f, 0.f);
        g_Apack[idx * 2 + 1] = make_float4(0.f, 0.f, 0.f, 0.f);
    }
}

// Cholesky (lower) of packed 6x6 SPD, in place. Returns product of pivots (= det),
// fills inv[j] = 1/L[j][j].
__device__ __forceinline__ float chol6(float* S, float* inv)
{
    float prod = 1.f;
    #pragma unroll
    for (int j = 0; j < LF; j++) {
        float s = S[IJ(j, j)];
        #pragma unroll
        for (int m = 0; m < j; m++) s = fmaf(-S[IJ(j, m)], S[IJ(j, m)], s);
        prod *= s;
        float rs = rsqrtf(s);
        inv[j] = rs;
        S[IJ(j, j)] = s * rs;
        #pragma unroll
        for (int i = j + 1; i < LF; i++) {
            float t = S[IJ(i, j)];
            #pragma unroll
            for (int m = 0; m < j; m++) t = fmaf(-S[IJ(i, m)], S[IJ(j, m)], t);
            S[IJ(i, j)] = t * rs;
        }
    }
    return prod;
}

__device__ __forceinline__ float fwd6(const float* L, const float* inv, const float* q, float* y)
{
    float ysq = 0.f;
    #pragma unroll
    for (int i = 0; i < LF; i++) {
        float t = q[i];
        #pragma unroll
        for (int m = 0; m < i; m++) t = fmaf(-L[IJ(i, m)], y[m], t);
        y[i] = t * inv[i];
        ysq = fmaf(y[i], y[i], ysq);
    }
    return ysq;
}

__global__ __launch_bounds__(THREADS, 3)
void mfa_main(const float* __restrict__ X, const int* __restrict__ J,
              const float* __restrict__ log_D, const float* __restrict__ PI,
              float* __restrict__ outPw, float* __restrict__ outM,
              float* __restrict__ outA, float* __restrict__ outD)
{
    __shared__ float4 s_in[DP];                // {jf0, jf1, xj0, xj1}
    __shared__ float  s_pi[KC];
    __shared__ float  s_bscore[NWARPS][NB];
    __shared__ int    s_bk[NWARPS][NB];
    __shared__ float  s_bPq[NWARPS][NB][27];   // raw P 21, q 6
    __shared__ float  s_mz[NB][LF];
    __shared__ float  s_Lzm[NB][21];
    __shared__ int    s_c[NB];

    const int tid  = threadIdx.x;
    const int lane = tid & 31;
    const int warp = tid >> 5;
    const int b0   = blockIdx.x * NB;

    for (int t = tid; t < DP; t += THREADS) {
        if (t < DFT) {
            float x0  = X[(size_t)b0 * DFT + t];
            float x1  = X[(size_t)(b0 + 1) * DFT + t];
            float jf0 = (J[(size_t)b0 * DFT + t] == 1) ? 1.0f : 0.0f;
            float jf1 = (J[(size_t)(b0 + 1) * DFT + t] == 1) ? 1.0f : 0.0f;
            s_in[t] = make_float4(jf0, jf1, x0 * jf0, x1 * jf1);
        } else {
            s_in[t] = make_float4(0.f, 0.f, 0.f, 0.f);
        }
    }
    for (int t = tid; t < KC; t += THREADS) s_pi[t] = PI[t];
    if (lane == 0) {
        s_bscore[warp][0] = -1e30f;
        s_bscore[warp][1] = -1e30f;
    }
    __syncthreads();

    // ---- Phase 1: per-(k, sample-pair) reductions; warp w owns k = w, w+5, ... (10 each) ----
    for (int k = warp; k < KC; k += NWARPS) {
        u64 acc[29];   // [0..20] P, [21..26] q, [27] quad, [28] Jf.logD -- packed {b0, b1}
        #pragma unroll
        for (int t = 0; t < 29; t++) acc[t] = 0ull;

        const float4* __restrict__ ap = g_Apack + (size_t)k * DP * 2;

        // software pipeline: preload iteration 0
        float4 v0  = ap[lane * 2 + 0];
        float4 v1  = ap[lane * 2 + 1];
        float4 sin = s_in[lane];

        #pragma unroll 5
        for (int t = 0; t < NITER; t++) {
            float4 c0 = v0, c1 = v1;
            float4 ci = sin;
            if (t < NITER - 1) {
                int dn = lane + 32 * (t + 1);   // < DP always
                v0  = ap[dn * 2 + 0];
                v1  = ap[dn * 2 + 1];
                sin = s_in[dn];
            }

            const float logD = c1.z, mu = c1.w;
            const float invD = exp2f(-1.44269504f * logD);

            u64 jf2 = pk2(ci.x, ci.y);
            u64 xj2 = pk2(ci.z, ci.w);
            u64 a2[LF] = { rep2(c0.x), rep2(c0.y), rep2(c0.z),
                           rep2(c0.w), rep2(c1.x), rep2(c1.y) };
            u64 invD2 = rep2(invD);

            u64 ia2[LF];
            #pragma unroll
            for (int i = 0; i < LF; i++) ia2[i] = mul2(invD2, a2[i]);

            u64 md2 = fma2(rep2(-mu), jf2, xj2);           // masked residual (pair)
            acc[27] = fma2(mul2(md2, md2), invD2, acc[27]); // quad
            acc[28] = fma2(jf2, rep2(logD), acc[28]);       // Jf . logD

            #pragma unroll
            for (int i = 0; i < LF; i++) {
                acc[21 + i] = fma2(md2, ia2[i], acc[21 + i]);   // q
                u64 ja = mul2(jf2, ia2[i]);
                #pragma unroll
                for (int j = 0; j <= i; j++)
                    acc[IJ(i, j)] = fma2(ja, a2[j], acc[IJ(i, j)]);  // P
            }
        }

        // Warp butterfly reduce on packed pairs
        #pragma unroll
        for (int t = 0; t < 29; t++) {
            u64 v = acc[t];
            #pragma unroll
            for (int off = 16; off > 0; off >>= 1)
                v = add2(v, __shfl_xor_sync(0xffffffffu, v, off));
            acc[t] = v;
        }

        if (lane == 0) {
            float av[29][NB];
            #pragma unroll
            for (int t = 0; t < 29; t++) upk2(acc[t], av[t][0], av[t][1]);
            #pragma unroll
            for (int b2 = 0; b2 < NB; b2++) {
                float P[21], q[LF];
                #pragma unroll
                for (int t = 0; t < 21; t++) P[t] = av[t][b2];
                #pragma unroll
                for (int i = 0; i < LF; i++) { P[IJ(i, i)] += 1.0f; q[i] = av[21 + i][b2]; }
                float inv[LF];
                float prod = chol6(P, inv);
                float y[LF];
                float ysq = fwd6(P, inv, q, y);
                float score = s_pi[k] - 0.5f * (av[27][b2] - ysq + __logf(prod) + av[28][b2]);
                if (score > s_bscore[warp][b2]) {
                    s_bscore[warp][b2] = score;
                    s_bk[warp][b2] = k;
                    #pragma unroll
                    for (int t = 0; t < 21; t++) s_bPq[warp][b2][t] = av[t][b2];
                    #pragma unroll
                    for (int i = 0; i < LF; i++) s_bPq[warp][b2][21 + i] = q[i];
                }
            }
        }
    }
    __syncthreads();

    // ---- Phase 2: per-sample small linalg (one thread per sample) ----
    if (tid < NB) {
        const int b2 = tid;
        float best = -1e30f; int bw = 0;
        for (int w = 0; w < NWARPS; w++)
            if (s_bscore[w][b2] > best) { best = s_bscore[w][b2]; bw = w; }
        s_c[b2] = s_bk[bw][b2];

        float P[21], q[LF];
        #pragma unroll
        for (int t = 0; t < 21; t++) P[t] = s_bPq[bw][b2][t];
        #pragma unroll
        for (int i = 0; i < LF; i++) { P[IJ(i, i)] += 1.0f; q[i] = s_bPq[bw][b2][21 + i]; }

        float inv[LF];
        (void)chol6(P, inv);                  // P -> L
        float y[LF];
        (void)fwd6(P, inv, q, y);
        float mz[LF];
        #pragma unroll
        for (int ii = LF - 1; ii >= 0; ii--) {
            float t = y[ii];
            #pragma unroll
            for (int m = ii + 1; m < LF; m++) t = fmaf(-P[IJ(m, ii)], mz[m], t);
            mz[ii] = t * inv[ii];
        }
        // Linv via forward substitution on identity
        float Li[21];
        #pragma unroll
        for (int j = 0; j < LF; j++) {
            Li[IJ(j, j)] = inv[j];
            #pragma unroll
            for (int i = j + 1; i < LF; i++) {
                float t = 0.f;
                #pragma unroll
                for (int m = j; m < i; m++) t = fmaf(P[IJ(i, m)], Li[IJ(m, j)], t);
                Li[IJ(i, j)] = -inv[i] * t;
            }
        }
        // cov = Linv^T Linv
        float C[21];
        #pragma unroll
        for (int i = 0; i < LF; i++)
            #pragma unroll
            for (int j = 0; j <= i; j++) {
                float t = 0.f;
                #pragma unroll
                for (int m = i; m < LF; m++) t = fmaf(Li[IJ(m, i)], Li[IJ(m, j)], t);
                C[IJ(i, j)] = t;
            }
        float invz[LF];
        (void)chol6(C, invz);                 // C -> Lz
        #pragma unroll
        for (int i = 0; i < LF; i++) s_mz[b2][i] = mz[i];
        #pragma unroll
        for (int t = 0; t < 21; t++) s_Lzm[b2][t] = C[t];
    }
    __syncthreads();

    // ---- Epilogue: stream outputs ----
    #pragma unroll
    for (int b2 = 0; b2 < NB; b2++) {
        const int b = b0 + b2;
        const int c = s_c[b2];
        float mz[LF], Lz[21];
        #pragma unroll
        for (int i = 0; i < LF; i++) mz[i] = s_mz[b2][i];
        #pragma unroll
        for (int t = 0; t < 21; t++) Lz[t] = s_Lzm[b2][t];
        const float4* __restrict__ apc = g_Apack + (size_t)c * DP * 2;
        for (int d = tid; d < DFT; d += THREADS) {
            float4 v0 = apc[d * 2 + 0];
            float4 v1 = apc[d * 2 + 1];
            float a[LF] = {v0.x, v0.y, v0.z, v0.w, v1.x, v1.y};
            float Mo = v1.w;   // mu
            #pragma unroll
            for (int i = 0; i < LF; i++) Mo = fmaf(a[i], mz[i], Mo);
            outM[(size_t)b * DFT + d] = Mo;
            float Ao[LF];
            #pragma unroll
            for (int j = 0; j < LF; j++) {
                float s = 0.f;
                #pragma unroll
                for (int i = j; i < LF; i++) s = fmaf(a[i], Lz[IJ(i, j)], s);
                Ao[j] = s;
            }
            float2* pA = reinterpret_cast<float2*>(outA + ((size_t)b * DFT + d) * LF);
            pA[0] = make_float2(Ao[0], Ao[1]);
            pA[1] = make_float2(Ao[2], Ao[3]);
            pA[2] = make_float2(Ao[4], Ao[5]);
            outD[(size_t)b * DFT + d] = expf(v1.z);   // exp(logD)
        }
    }
    if (tid < NB) outPw[b0 + tid] = 1.0f;
}

extern "C" void kernel_launch(void* const* d_in, const int* in_sizes, int n_in,
                              void* d_out, int out_size)
{
    const float* X      = (const float*)d_in[0];
    const int*   J      = (const int*)  d_in[1];
    const float* MU     = (const float*)d_in[2];
    const float* A_fac  = (const float*)d_in[3];
    const float* log_D  = (const float*)d_in[4];
    const float* PI     = (const float*)d_in[5];
    float* out = (float*)d_out;

    const int B = in_sizes[0] / DFT;     // 2048
    float* outPw = out;
    float* outM  = out + B;
    float* outA  = outM + (size_t)B * DFT;
    float* outD  = outA + (size_t)B * DFT * LF;

    pack_kernel<<<(KC * DP + 255) / 256, 256>>>(A_fac, MU, log_D);
    mfa_main<<<B / NB, THREADS>>>(X, J, log_D, PI, outPw, outM, outA, outD);
}

// round 3
// speedup vs baseline: 1.4860x; 1.1135x over previous
#include <cuda_runtime.h>

#define DFT 784
#define DP  800              // padded feature dim (zero-padded tail)
#define PAD 64               // over-allocation so prefetch needs no guard
#define KC  50
#define LF  6
#define NB  2
#define THREADS 160
#define NWARPS (THREADS/32)  // 5 -> each warp does exactly 10 components
#define NITER 25             // DP/32

typedef unsigned long long u64;

// SoA packed operands, coalesced per warp:
//  g_C0[k*DP+d] = {c0,c1,c2,c3},  g_C1[k*DP+d] = {c4,c5,s,nsmu},  g_LD[k*DP+d] = logD
// where c_i = sqrt(invD)*a_i, s = sqrt(invD), nsmu = -s*mu.
__device__ __align__(16) float4 g_C0[KC * DP + PAD];
__device__ __align__(16) float4 g_C1[KC * DP + PAD];
__device__ float g_LD[KC * DP + PAD];

__device__ __forceinline__ constexpr int IJ(int i, int j) { return i * (i + 1) / 2 + j; }

// ---- f32x2 packed helpers ----
__device__ __forceinline__ u64 pk2(float a, float b) {
    u64 r; asm("mov.b64 %0,{%1,%2};" : "=l"(r) : "f"(a), "f"(b)); return r;
}
__device__ __forceinline__ u64 rep2(float a) { return pk2(a, a); }
__device__ __forceinline__ void upk2(u64 v, float& a, float& b) {
    asm("mov.b64 {%0,%1},%2;" : "=f"(a), "=f"(b) : "l"(v));
}
__device__ __forceinline__ u64 fma2(u64 a, u64 b, u64 c) {
    u64 d; asm("fma.rn.f32x2 %0,%1,%2,%3;" : "=l"(d) : "l"(a), "l"(b), "l"(c)); return d;
}
__device__ __forceinline__ u64 mul2(u64 a, u64 b) {
    u64 d; asm("mul.rn.f32x2 %0,%1,%2;" : "=l"(d) : "l"(a), "l"(b)); return d;
}
__device__ __forceinline__ u64 add2(u64 a, u64 b) {
    u64 d; asm("add.rn.f32x2 %0,%1,%2;" : "=l"(d) : "l"(a), "l"(b)); return d;
}

__global__ void pack_kernel(const float* __restrict__ A_fac,
                            const float* __restrict__ MU,
                            const float* __restrict__ log_D)
{
    int idx = blockIdx.x * blockDim.x + threadIdx.x;
    if (idx >= KC * DP + PAD) return;
    int k = idx / DP, d = idx - k * DP;
    if (k < KC && d < DFT) {
        int src = k * DFT + d;
        const float* a = A_fac + (size_t)src * LF;
        float ld = log_D[src];
        float s  = expf(-0.5f * ld);       // sqrt(invD)
        g_C0[idx] = make_float4(s * a[0], s * a[1], s * a[2], s * a[3]);
        g_C1[idx] = make_float4(s * a[4], s * a[5], s, -s * MU[src]);
        g_LD[idx] = ld;
    } else {
        g_C0[idx] = make_float4(0.f, 0.f, 0.f, 0.f);
        g_C1[idx] = make_float4(0.f, 0.f, 0.f, 0.f);
        g_LD[idx] = 0.f;
    }
}

// Cholesky (lower) of packed 6x6 SPD, in place. Returns product of pivots (= det),
// fills inv[j] = 1/L[j][j].
__device__ __forceinline__ float chol6(float* S, float* inv)
{
    float prod = 1.f;
    #pragma unroll
    for (int j = 0; j < LF; j++) {
        float s = S[IJ(j, j)];
        #pragma unroll
        for (int m = 0; m < j; m++) s = fmaf(-S[IJ(j, m)], S[IJ(j, m)], s);
        prod *= s;
        float rs = rsqrtf(s);
        inv[j] = rs;
        S[IJ(j, j)] = s * rs;
        #pragma unroll
        for (int i = j + 1; i < LF; i++) {
            float t = S[IJ(i, j)];
            #pragma unroll
            for (int m = 0; m < j; m++) t = fmaf(-S[IJ(i, m)], S[IJ(j, m)], t);
            S[IJ(i, j)] = t * rs;
        }
    }
    return prod;
}

__device__ __forceinline__ float fwd6(const float* L, const float* inv, const float* q, float* y)
{
    float ysq = 0.f;
    #pragma unroll
    for (int i = 0; i < LF; i++) {
        float t = q[i];
        #pragma unroll
        for (int m = 0; m < i; m++) t = fmaf(-L[IJ(i, m)], y[m], t);
        y[i] = t * inv[i];
        ysq = fmaf(y[i], y[i], ysq);
    }
    return ysq;
}

struct Slot { float4 v0, v1, in; float ld; };

__device__ __forceinline__ void load_slot(Slot& s, const float4* __restrict__ p0,
                                          const float4* __restrict__ p1,
                                          const float*  __restrict__ pl,
                                          const float4* __restrict__ sin, int d)
{
    s.v0 = p0[d]; s.v1 = p1[d]; s.ld = pl[d]; s.in = sin[d];
}

__device__ __forceinline__ void consume(const Slot& c, u64* acc)
{
    u64 jf2 = pk2(c.in.x, c.in.y);
    u64 xj2 = pk2(c.in.z, c.in.w);
    u64 c2[LF] = { rep2(c.v0.x), rep2(c.v0.y), rep2(c.v0.z),
                   rep2(c.v0.w), rep2(c.v1.x), rep2(c.v1.y) };
    u64 s2    = rep2(c.v1.z);
    u64 nsmu2 = rep2(c.v1.w);
    u64 ld2   = rep2(c.ld);

    u64 e2 = fma2(nsmu2, jf2, mul2(s2, xj2));      // sqrt(invD) * masked residual
    acc[27] = fma2(e2, e2, acc[27]);               // quad
    acc[28] = fma2(jf2, ld2, acc[28]);             // Jf . logD

    #pragma unroll
    for (int i = 0; i < LF; i++) {
        acc[21 + i] = fma2(e2, c2[i], acc[21 + i]);    // q
        u64 jc = mul2(jf2, c2[i]);
        #pragma unroll
        for (int j = 0; j <= i; j++)
            acc[IJ(i, j)] = fma2(jc, c2[j], acc[IJ(i, j)]);  // P
    }
}

__global__ __launch_bounds__(THREADS, 3)
void mfa_main(const float* __restrict__ X, const int* __restrict__ J,
              const float* __restrict__ MU, const float* __restrict__ A_fac,
              const float* __restrict__ log_D, const float* __restrict__ PI,
              float* __restrict__ outPw, float* __restrict__ outM,
              float* __restrict__ outA, float* __restrict__ outD)
{
    __shared__ float4 s_in[DP + PAD];          // {jf0, jf1, xj0, xj1}
    __shared__ float  s_pi[KC];
    __shared__ float  s_bscore[NWARPS][NB];
    __shared__ int    s_bk[NWARPS][NB];
    __shared__ float  s_bPq[NWARPS][NB][27];
    __shared__ float  s_mz[NB][LF];
    __shared__ float  s_Lzm[NB][21];
    __shared__ int    s_c[NB];

    const int tid  = threadIdx.x;
    const int lane = tid & 31;
    const int warp = tid >> 5;
    const int b0   = blockIdx.x * NB;

    for (int t = tid; t < DP + PAD; t += THREADS) {
        if (t < DFT) {
            float x0  = X[(size_t)b0 * DFT + t];
            float x1  = X[(size_t)(b0 + 1) * DFT + t];
            float jf0 = (J[(size_t)b0 * DFT + t] == 1) ? 1.0f : 0.0f;
            float jf1 = (J[(size_t)(b0 + 1) * DFT + t] == 1) ? 1.0f : 0.0f;
            s_in[t] = make_float4(jf0, jf1, x0 * jf0, x1 * jf1);
        } else {
            s_in[t] = make_float4(0.f, 0.f, 0.f, 0.f);
        }
    }
    for (int t = tid; t < KC; t += THREADS) s_pi[t] = PI[t];
    if (lane == 0) {
        s_bscore[warp][0] = -1e30f;
        s_bscore[warp][1] = -1e30f;
    }
    __syncthreads();

    // ---- Phase 1: warp w owns k = w, w+5, ... (10 components each) ----
    for (int k = warp; k < KC; k += NWARPS) {
        u64 acc[29];
        #pragma unroll
        for (int t = 0; t < 29; t++) acc[t] = 0ull;

        const float4* __restrict__ p0 = g_C0 + (size_t)k * DP;
        const float4* __restrict__ p1 = g_C1 + (size_t)k * DP;
        const float*  __restrict__ pl = g_LD + (size_t)k * DP;

        Slot s0, s1;
        load_slot(s0, p0, p1, pl, s_in, lane);
        load_slot(s1, p0, p1, pl, s_in, lane + 32);

        // 12 double-iterations + 1 tail (NITER = 25). Prefetch distance 2;
        // arrays padded so d+64 reads are always in-bounds.
        #pragma unroll 2
        for (int t = 0; t < NITER - 1; t += 2) {
            int d = lane + 32 * t;
            Slot c0 = s0;
            load_slot(s0, p0, p1, pl, s_in, d + 64);
            consume(c0, acc);
            Slot c1 = s1;
            load_slot(s1, p0, p1, pl, s_in, d + 96);
            consume(c1, acc);
        }
        consume(s0, acc);   // t = 24

        // Warp butterfly reduce on packed pairs
        #pragma unroll
        for (int t = 0; t < 29; t++) {
            u64 v = acc[t];
            #pragma unroll
            for (int off = 16; off > 0; off >>= 1)
                v = add2(v, __shfl_xor_sync(0xffffffffu, v, off));
            acc[t] = v;
        }

        if (lane == 0) {
            float av[29][NB];
            #pragma unroll
            for (int t = 0; t < 29; t++) upk2(acc[t], av[t][0], av[t][1]);
            #pragma unroll
            for (int b2 = 0; b2 < NB; b2++) {
                float P[21], q[LF];
                #pragma unroll
                for (int t = 0; t < 21; t++) P[t] = av[t][b2];
                #pragma unroll
                for (int i = 0; i < LF; i++) { P[IJ(i, i)] += 1.0f; q[i] = av[21 + i][b2]; }
                float inv[LF];
                float prod = chol6(P, inv);
                float y[LF];
                float ysq = fwd6(P, inv, q, y);
                float score = s_pi[k] - 0.5f * (av[27][b2] - ysq + __logf(prod) + av[28][b2]);
                if (score > s_bscore[warp][b2]) {
                    s_bscore[warp][b2] = score;
                    s_bk[warp][b2] = k;
                    #pragma unroll
                    for (int t = 0; t < 21; t++) s_bPq[warp][b2][t] = av[t][b2];
                    #pragma unroll
                    for (int i = 0; i < LF; i++) s_bPq[warp][b2][21 + i] = q[i];
                }
            }
        }
    }
    __syncthreads();

    // ---- Phase 2: per-sample small linalg ----
    if (tid < NB) {
        const int b2 = tid;
        float best = -1e30f; int bw = 0;
        for (int w = 0; w < NWARPS; w++)
            if (s_bscore[w][b2] > best) { best = s_bscore[w][b2]; bw = w; }
        s_c[b2] = s_bk[bw][b2];

        float P[21], q[LF];
        #pragma unroll
        for (int t = 0; t < 21; t++) P[t] = s_bPq[bw][b2][t];
        #pragma unroll
        for (int i = 0; i < LF; i++) { P[IJ(i, i)] += 1.0f; q[i] = s_bPq[bw][b2][21 + i]; }

        float inv[LF];
        (void)chol6(P, inv);
        float y[LF];
        (void)fwd6(P, inv, q, y);
        float mz[LF];
        #pragma unroll
        for (int ii = LF - 1; ii >= 0; ii--) {
            float t = y[ii];
            #pragma unroll
            for (int m = ii + 1; m < LF; m++) t = fmaf(-P[IJ(m, ii)], mz[m], t);
            mz[ii] = t * inv[ii];
        }
        float Li[21];
        #pragma unroll
        for (int j = 0; j < LF; j++) {
            Li[IJ(j, j)] = inv[j];
            #pragma unroll
            for (int i = j + 1; i < LF; i++) {
                float t = 0.f;
                #pragma unroll
                for (int m = j; m < i; m++) t = fmaf(P[IJ(i, m)], Li[IJ(m, j)], t);
                Li[IJ(i, j)] = -inv[i] * t;
            }
        }
        float C[21];
        #pragma unroll
        for (int i = 0; i < LF; i++)
            #pragma unroll
            for (int j = 0; j <= i; j++) {
                float t = 0.f;
                #pragma unroll
                for (int m = i; m < LF; m++) t = fmaf(Li[IJ(m, i)], Li[IJ(m, j)], t);
                C[IJ(i, j)] = t;
            }
        float invz[LF];
        (void)chol6(C, invz);
        #pragma unroll
        for (int i = 0; i < LF; i++) s_mz[b2][i] = mz[i];
        #pragma unroll
        for (int t = 0; t < 21; t++) s_Lzm[b2][t] = C[t];
    }
    __syncthreads();

    // ---- Epilogue: stream outputs (read exact original inputs) ----
    #pragma unroll
    for (int b2 = 0; b2 < NB; b2++) {
        const int b = b0 + b2;
        const int c = s_c[b2];
        float mz[LF], Lz[21];
        #pragma unroll
        for (int i = 0; i < LF; i++) mz[i] = s_mz[b2][i];
        #pragma unroll
        for (int t = 0; t < 21; t++) Lz[t] = s_Lzm[b2][t];
        const float* __restrict__ ac  = A_fac + (size_t)c * DFT * LF;
        const float* __restrict__ muc = MU    + (size_t)c * DFT;
        const float* __restrict__ ldc = log_D + (size_t)c * DFT;
        for (int d = tid; d < DFT; d += THREADS) {
            const float2* ar = reinterpret_cast<const float2*>(ac + (size_t)d * LF);
            float2 r0 = ar[0], r1 = ar[1], r2 = ar[2];
            float a[LF] = {r0.x, r0.y, r1.x, r1.y, r2.x, r2.y};
            float Mo = muc[d];
            #pragma unroll
            for (int i = 0; i < LF; i++) Mo = fmaf(a[i], mz[i], Mo);
            outM[(size_t)b * DFT + d] = Mo;
            float Ao[LF];
            #pragma unroll
            for (int j = 0; j < LF; j++) {
                float s = 0.f;
                #pragma unroll
                for (int i = j; i < LF; i++) s = fmaf(a[i], Lz[IJ(i, j)], s);
                Ao[j] = s;
            }
            float2* pA = reinterpret_cast<float2*>(outA + ((size_t)b * DFT + d) * LF);
            pA[0] = make_float2(Ao[0], Ao[1]);
            pA[1] = make_float2(Ao[2], Ao[3]);
            pA[2] = make_float2(Ao[4], Ao[5]);
            outD[(size_t)b * DFT + d] = expf(ldc[d]);
        }
    }
    if (tid < NB) outPw[b0 + tid] = 1.0f;
}

extern "C" void kernel_launch(void* const* d_in, const int* in_sizes, int n_in,
                              void* d_out, int out_size)
{
    const float* X      = (const float*)d_in[0];
    const int*   J      = (const int*)  d_in[1];
    const float* MU     = (const float*)d_in[2];
    const float* A_fac  = (const float*)d_in[3];
    const float* log_D  = (const float*)d_in[4];
    const float* PI     = (const float*)d_in[5];
    float* out = (float*)d_out;

    const int B = in_sizes[0] / DFT;     // 2048
    float* outPw = out;
    float* outM  = out + B;
    float* outA  = outM + (size_t)B * DFT;
    float* outD  = outA + (size_t)B * DFT * LF;

    pack_kernel<<<(KC * DP + PAD + 255) / 256, 256>>>(A_fac, MU, log_D);
    mfa_main<<<B / NB, THREADS>>>(X, J, MU, A_fac, log_D, PI, outPw, outM, outA, outD);
}